// round 15
// baseline (speedup 1.0000x reference)
#include <cuda_runtime.h>

// mean(cumsum(per_sample)) == (1/B) * sum_i per_sample[i] * (B - i)
// Single-pass weighted reduction; single kernel, last-block finalize.
// OCCUPANCY EXPERIMENT: 8 blocks/SM (<=32 regs via launch_bounds),
// GRID = 1184 = 148 * 8 -> one wave at 64 warps/SM. Structure otherwise
// identical to the proven 81.9us kernel (x2 unroll, 4 LDG.128 in flight).
// Observed trend: 40 warps -> DRAM 80.4%, 48 -> 81.3%; testing 64.

#define WBCE_EPS 1e-10f
#define GRID_MAIN 1184
#define THREADS_MAIN 256

__device__ double g_partials[GRID_MAIN];
__device__ unsigned int g_done = 0;   // self-resets via atomicInc wraparound

__device__ __forceinline__ float elem_term(float l, float t, float wN, float dP) {
    // t is exactly 0.0f or 1.0f; dead branch contributes exactly 0.
    // w = t ? wp : wn  ==  wn + t*(wp-wn)   (exact for t in {0,1})
    float x = (t != 0.0f) ? l : (1.0f - l);
    float w = fmaf(t, dP, wN);
    return w * __logf(x + WBCE_EPS);
}

__global__ __launch_bounds__(THREADS_MAIN, 8) void wbce_fused_kernel(
    const float* __restrict__ logits,
    const float* __restrict__ targets,
    const float* __restrict__ wp,
    const float* __restrict__ wn,
    float* __restrict__ out,
    int N4)   // float4 groups = B*2 (C=8 -> 2 groups per row), fits int32
{
    __shared__ float swn[8];
    __shared__ float sdp[8];   // wp - wn
    if (threadIdx.x < 8) {
        float a = wp[threadIdx.x];
        float b = wn[threadIdx.x];
        swn[threadIdx.x] = b;
        sdp[threadIdx.x] = a - b;
    }
    __syncthreads();

    const int stride = GRID_MAIN * THREADS_MAIN;            // even
    const int tid = blockIdx.x * THREADS_MAIN + threadIdx.x;

    // Channel half (0..3 or 4..7) fixed per thread (stride even).
    const int cb = (tid & 1) * 4;
    const float n0 = swn[cb + 0], n1 = swn[cb + 1], n2 = swn[cb + 2], n3 = swn[cb + 3];
    const float d0 = sdp[cb + 0], d1 = sdp[cb + 1], d2 = sdp[cb + 2], d3 = sdp[cb + 3];

    const float4* __restrict__ lg = (const float4*)logits;
    const float4* __restrict__ tg = (const float4*)targets;

    const int B = N4 >> 1;
    // Row weight (B - i): integer <= 2^23, exact in fp32 throughout.
    float wrow = (float)(B - (tid >> 1));
    const float wstep = (float)(stride >> 1);
    const int stride2 = 2 * stride;

    double acc = 0.0;
    int idx = tid;

    // Unroll x2: 4 independent LDG.128 in flight per thread.
    for (; idx + stride < N4; idx += stride2) {
        float4 l0 = __ldg(lg + idx);
        float4 t0 = __ldg(tg + idx);
        float4 l1 = __ldg(lg + idx + stride);
        float4 t1 = __ldg(tg + idx + stride);

        float s0 = elem_term(l0.x, t0.x, n0, d0)
                 + elem_term(l0.y, t0.y, n1, d1)
                 + elem_term(l0.z, t0.z, n2, d2)
                 + elem_term(l0.w, t0.w, n3, d3);
        float s1 = elem_term(l1.x, t1.x, n0, d0)
                 + elem_term(l1.y, t1.y, n1, d1)
                 + elem_term(l1.z, t1.z, n2, d2)
                 + elem_term(l1.w, t1.w, n3, d3);

        // wrow*s0 + (wrow - wstep)*s1, all fp32; one double add per pair.
        float prod = fmaf(wrow, s0, (wrow - wstep) * s1);
        acc -= (double)prod;
        wrow -= 2.0f * wstep;
    }
    if (idx < N4) {
        float4 l0 = __ldg(lg + idx);
        float4 t0 = __ldg(tg + idx);
        float s0 = elem_term(l0.x, t0.x, n0, d0)
                 + elem_term(l0.y, t0.y, n1, d1)
                 + elem_term(l0.z, t0.z, n2, d2)
                 + elem_term(l0.w, t0.w, n3, d3);
        acc -= (double)(wrow * s0);
    }

    // ---- block reduce (double) ----
    #pragma unroll
    for (int off = 16; off > 0; off >>= 1)
        acc += __shfl_down_sync(0xffffffffu, acc, off);

    __shared__ double ssum[THREADS_MAIN / 32];
    const int warp = threadIdx.x >> 5;
    if ((threadIdx.x & 31) == 0) ssum[warp] = acc;
    __syncthreads();

    // ---- last-block finalize ----
    __shared__ bool s_last;
    if (threadIdx.x == 0) {
        double b = 0.0;
        #pragma unroll
        for (int w = 0; w < THREADS_MAIN / 32; w++) b += ssum[w];
        g_partials[blockIdx.x] = b;
        __threadfence();
        unsigned int old = atomicInc(&g_done, GRID_MAIN - 1);  // wraps to 0
        s_last = (old == GRID_MAIN - 1);
    }
    __syncthreads();

    if (s_last) {
        __threadfence();
        volatile double* vp = g_partials;
        double a = 0.0;
        for (int i = threadIdx.x; i < GRID_MAIN; i += THREADS_MAIN)
            a += vp[i];

        #pragma unroll
        for (int off = 16; off > 0; off >>= 1)
            a += __shfl_down_sync(0xffffffffu, a, off);

        if ((threadIdx.x & 31) == 0) ssum[warp] = a;
        __syncthreads();

        if (threadIdx.x == 0) {
            double tot = 0.0;
            #pragma unroll
            for (int w = 0; w < THREADS_MAIN / 32; w++) tot += ssum[w];
            out[0] = (float)(tot / (double)B);
        }
    }
}

extern "C" void kernel_launch(void* const* d_in, const int* in_sizes, int n_in,
                              void* d_out, int out_size) {
    const float* logits  = (const float*)d_in[0];
    const float* targets = (const float*)d_in[1];
    const float* wp      = (const float*)d_in[2];
    const float* wn      = (const float*)d_in[3];

    const int n_elem = in_sizes[0];   // B * 8 = 2^26, fits int32
    const int N4 = n_elem >> 2;       // float4 groups

    wbce_fused_kernel<<<GRID_MAIN, THREADS_MAIN>>>(logits, targets, wp, wn,
                                                   (float*)d_out, N4);
}

// round 16
// speedup vs baseline: 1.0250x; 1.0250x over previous
#include <cuda_runtime.h>

// mean(cumsum(per_sample)) == (1/B) * sum_i per_sample[i] * (B - i)
// Single-pass weighted reduction; single kernel, last-block finalize.
// GRID = 888 = 148 SMs * 6 blocks (<=40 regs via launch_bounds, 256 thr)
// -> exactly ONE wave at 48 warps/SM. Plain __ldg LDG.128 loads.
//
// FINAL. Measured 81.9-82.1us across four runs (DRAM 81%, 6.65 TB/s =
// practical HBM ceiling for this 537 MB read-once stream). Full sweep of
// alternatives regressed: 64-warp/32-reg occupancy +2us (spills),
// __ldcs +4us, block chunk-steal +14us, v8.f32 loads +24us, warp
// chunk-steal +36us (single-address atomic serialization).

#define WBCE_EPS 1e-10f
#define GRID_MAIN 888
#define THREADS_MAIN 256

__device__ double g_partials[GRID_MAIN];
__device__ unsigned int g_done = 0;   // self-resets via atomicInc wraparound

__device__ __forceinline__ float elem_term(float l, float t, float wP, float wN) {
    // t is exactly 0.0f or 1.0f; dead branch contributes exactly 0
    bool pos = (t != 0.0f);
    float x = pos ? l : (1.0f - l);
    float w = pos ? wP : wN;
    return w * __logf(x + WBCE_EPS);
}

__global__ __launch_bounds__(THREADS_MAIN, 6) void wbce_fused_kernel(
    const float* __restrict__ logits,
    const float* __restrict__ targets,
    const float* __restrict__ wp,
    const float* __restrict__ wn,
    float* __restrict__ out,
    int N4)   // float4 groups = B*2 (C=8 -> 2 groups per row), fits int32
{
    __shared__ float swp[8];
    __shared__ float swn[8];
    if (threadIdx.x < 8) {
        swp[threadIdx.x] = wp[threadIdx.x];
        swn[threadIdx.x] = wn[threadIdx.x];
    }
    __syncthreads();

    const int stride = GRID_MAIN * THREADS_MAIN;            // even
    const int tid = blockIdx.x * THREADS_MAIN + threadIdx.x;

    // Channel half (0..3 or 4..7) fixed per thread (stride even).
    const int cb = (tid & 1) * 4;
    const float w0p = swp[cb + 0], w1p = swp[cb + 1], w2p = swp[cb + 2], w3p = swp[cb + 3];
    const float w0n = swn[cb + 0], w1n = swn[cb + 1], w2n = swn[cb + 2], w3n = swn[cb + 3];

    const float4* __restrict__ lg = (const float4*)logits;
    const float4* __restrict__ tg = (const float4*)targets;

    const int B = N4 >> 1;
    // Row weight (B - i): integer <= 2^23, exact in fp32 throughout.
    float wrow = (float)(B - (tid >> 1));
    const float wstep = (float)(stride >> 1);

    double acc = 0.0;
    int idx = tid;

    // Unroll x2: 4 independent LDG.128 in flight per thread.
    for (; idx + stride < N4; idx += 2 * stride) {
        float4 l0 = __ldg(lg + idx);
        float4 t0 = __ldg(tg + idx);
        float4 l1 = __ldg(lg + idx + stride);
        float4 t1 = __ldg(tg + idx + stride);

        float s0 = elem_term(l0.x, t0.x, w0p, w0n)
                 + elem_term(l0.y, t0.y, w1p, w1n)
                 + elem_term(l0.z, t0.z, w2p, w2n)
                 + elem_term(l0.w, t0.w, w3p, w3n);
        float s1 = elem_term(l1.x, t1.x, w0p, w0n)
                 + elem_term(l1.y, t1.y, w1p, w1n)
                 + elem_term(l1.z, t1.z, w2p, w2n)
                 + elem_term(l1.w, t1.w, w3p, w3n);

        // wrow*s0 + (wrow - wstep)*s1, all fp32; one double add per pair.
        float prod = fmaf(wrow, s0, (wrow - wstep) * s1);
        acc -= (double)prod;
        wrow -= 2.0f * wstep;
    }
    if (idx < N4) {
        float4 l0 = __ldg(lg + idx);
        float4 t0 = __ldg(tg + idx);
        float s0 = elem_term(l0.x, t0.x, w0p, w0n)
                 + elem_term(l0.y, t0.y, w1p, w1n)
                 + elem_term(l0.z, t0.z, w2p, w2n)
                 + elem_term(l0.w, t0.w, w3p, w3n);
        acc -= (double)(wrow * s0);
    }

    // ---- block reduce (double) ----
    #pragma unroll
    for (int off = 16; off > 0; off >>= 1)
        acc += __shfl_down_sync(0xffffffffu, acc, off);

    __shared__ double ssum[THREADS_MAIN / 32];
    const int warp = threadIdx.x >> 5;
    if ((threadIdx.x & 31) == 0) ssum[warp] = acc;
    __syncthreads();

    // ---- last-block finalize ----
    __shared__ bool s_last;
    if (threadIdx.x == 0) {
        double b = 0.0;
        #pragma unroll
        for (int w = 0; w < THREADS_MAIN / 32; w++) b += ssum[w];
        g_partials[blockIdx.x] = b;
        __threadfence();
        unsigned int old = atomicInc(&g_done, GRID_MAIN - 1);  // wraps to 0
        s_last = (old == GRID_MAIN - 1);
    }
    __syncthreads();

    if (s_last) {
        __threadfence();
        volatile double* vp = g_partials;
        double a = 0.0;
        for (int i = threadIdx.x; i < GRID_MAIN; i += THREADS_MAIN)
            a += vp[i];

        #pragma unroll
        for (int off = 16; off > 0; off >>= 1)
            a += __shfl_down_sync(0xffffffffu, a, off);

        if ((threadIdx.x & 31) == 0) ssum[warp] = a;
        __syncthreads();

        if (threadIdx.x == 0) {
            double tot = 0.0;
            #pragma unroll
            for (int w = 0; w < THREADS_MAIN / 32; w++) tot += ssum[w];
            out[0] = (float)(tot / (double)B);
        }
    }
}

extern "C" void kernel_launch(void* const* d_in, const int* in_sizes, int n_in,
                              void* d_out, int out_size) {
    const float* logits  = (const float*)d_in[0];
    const float* targets = (const float*)d_in[1];
    const float* wp      = (const float*)d_in[2];
    const float* wn      = (const float*)d_in[3];

    const int n_elem = in_sizes[0];   // B * 8 = 2^26, fits int32
    const int N4 = n_elem >> 2;       // float4 groups

    wbce_fused_kernel<<<GRID_MAIN, THREADS_MAIN>>>(logits, targets, wp, wn,
                                                   (float*)d_out, N4);
}